// round 1
// baseline (speedup 1.0000x reference)
#include <cuda_runtime.h>
#include <cuda_bf16.h>

#define BATCH 16
#define DIMC  256
#define NHEAD 8
#define CPH   8
#define CRCH  64
#define HH    64
#define WW    64
#define NPIX  (HH*WW)
#define QKVC  192   // 3*CR
#define SCALE 0.17677669529663687f  // (256/8)^-0.5

// Scratch (device globals are the allowed scratch mechanism)
__device__ float g_qkv[(long)BATCH * QKVC * NPIX];  // (B, 192, 64, 64)
__device__ float g_att[(long)BATCH * CRCH * NPIX];  // (B, 64, 64, 64)

// ---------------------------------------------------------------------------
// Generic batched SGEMM: C[b] = A (MxK, shared) * B[b] (KxN) + bias[m]
// BM=64, BN=128, BK=16, 256 threads, 4x8 register tile per thread.
// ---------------------------------------------------------------------------
__global__ __launch_bounds__(256)
void sgemm_kernel(const float* __restrict__ A, const float* __restrict__ B,
                  const float* __restrict__ bias, float* __restrict__ C,
                  int M, int N, int K, long strideB, long strideC)
{
    const int BM = 64, BN = 128, BK = 16;
    __shared__ float As[16][65];   // padded (transposed store)
    __shared__ float Bs[16][128];

    int bx = blockIdx.x, by = blockIdx.y, bz = blockIdx.z;
    const float* Bp = B + (long)bz * strideB;
    float*       Cp = C + (long)bz * strideC;

    int tid = threadIdx.x;
    int tx = tid & 15;        // n-dir (16)
    int ty = tid >> 4;        // m-dir (16)
    int m0 = by * BM, n0 = bx * BN;

    // A-load mapping: one float4 along K per thread
    int aRow = tid >> 2;          // 0..63
    int aCol = (tid & 3) * 4;     // 0,4,8,12

    float acc[4][8];
    #pragma unroll
    for (int i = 0; i < 4; i++)
        #pragma unroll
        for (int j = 0; j < 8; j++) acc[i][j] = 0.f;

    for (int k0 = 0; k0 < K; k0 += BK) {
        float4 av = *(const float4*)(A + (long)(m0 + aRow) * K + k0 + aCol);
        As[aCol + 0][aRow] = av.x;
        As[aCol + 1][aRow] = av.y;
        As[aCol + 2][aRow] = av.z;
        As[aCol + 3][aRow] = av.w;
        #pragma unroll
        for (int q = 0; q < 2; q++) {
            int idx  = tid + q * 256;
            int bRow = idx >> 5;          // 0..15
            int bCol = (idx & 31) * 4;    // 0..124
            float4 bv = *(const float4*)(Bp + (long)(k0 + bRow) * N + n0 + bCol);
            *(float4*)&Bs[bRow][bCol] = bv;
        }
        __syncthreads();

        #pragma unroll
        for (int k = 0; k < BK; k++) {
            float a[4], b[8];
            #pragma unroll
            for (int i = 0; i < 4; i++) a[i] = As[k][ty * 4 + i];
            #pragma unroll
            for (int j = 0; j < 4; j++) b[j]     = Bs[k][tx * 4 + j];
            #pragma unroll
            for (int j = 0; j < 4; j++) b[4 + j] = Bs[k][64 + tx * 4 + j];
            #pragma unroll
            for (int i = 0; i < 4; i++)
                #pragma unroll
                for (int j = 0; j < 8; j++)
                    acc[i][j] += a[i] * b[j];
        }
        __syncthreads();
    }

    #pragma unroll
    for (int i = 0; i < 4; i++) {
        int m = m0 + ty * 4 + i;
        float bsv = bias[m];
        float4 v0 = make_float4(acc[i][0] + bsv, acc[i][1] + bsv,
                                acc[i][2] + bsv, acc[i][3] + bsv);
        float4 v1 = make_float4(acc[i][4] + bsv, acc[i][5] + bsv,
                                acc[i][6] + bsv, acc[i][7] + bsv);
        *(float4*)(Cp + (long)m * N + n0 + tx * 4)      = v0;
        *(float4*)(Cp + (long)m * N + n0 + 64 + tx * 4) = v1;
    }
}

// ---------------------------------------------------------------------------
// Slide attention: per (b, nh, pixel):
//   k[c,t] = nb_k[t] + (b0+b1)[c*9+t] + rpb[nh,t] + sum_s W1[c*9+t,s]*nb_k[s]
//   logit[t] = sum_c q[c]*SCALE * k[c,t];  attn = softmax_t(logit)
//   v[c,t] analogous (no rpb);  out[c] = sum_t attn[t]*v[c,t]
// Block: 256 threads, 16x32 pixel tile, 2 pixels/thread (amortize weight LDS).
// ---------------------------------------------------------------------------
__global__ __launch_bounds__(256)
void attn_kernel(const float* __restrict__ qkv,
                 const float* __restrict__ dep_b0,
                 const float* __restrict__ dep_b1,
                 const float* __restrict__ W1,
                 const float* __restrict__ rpb,
                 float* __restrict__ att)
{
    __shared__ float sk[CPH][18][34];
    __shared__ float sv[CPH][18][34];
    __shared__ float sw1[72][9];
    __shared__ float sb[72];
    __shared__ float srpb[9];

    int bz = blockIdx.z;
    int b  = bz >> 3, nh = bz & 7;
    int x0 = blockIdx.x * 32, y0 = blockIdx.y * 16;
    int tid = threadIdx.x;
    int tx = tid & 15, ty = tid >> 4;

    const float* base = qkv + ((long)b * QKVC + 24 * nh) * NPIX;

    // Halo load: kk = channels 8..15, vv = channels 16..23 (within this head)
    for (int i = tid; i < 8 * 18 * 34; i += 256) {
        int c   = i / (18 * 34);
        int r   = (i / 34) % 18;
        int col = i % 34;
        int gy = y0 + r - 1, gx = x0 + col - 1;
        float kv = 0.f, vv = 0.f;
        if (gy >= 0 && gy < HH && gx >= 0 && gx < WW) {
            long off = (long)(8 + c) * NPIX + gy * WW + gx;
            kv = base[off];
            vv = base[off + 8 * NPIX];
        }
        sk[c][r][col] = kv;
        sv[c][r][col] = vv;
    }
    if (tid < 72) sb[tid] = dep_b0[tid] + dep_b1[tid];
    for (int i = tid; i < 72 * 9; i += 256) sw1[i / 9][i % 9] = W1[i];
    if (tid < 9) srpb[tid] = rpb[nh * 9 + tid];
    __syncthreads();

    int pA = (y0 + ty) * WW + (x0 + tx);
    int pB = pA + 16;
    int ly = ty + 1, lxA = tx + 1, lxB = tx + 17;

    float logA[9], logB[9];
    #pragma unroll
    for (int t = 0; t < 9; t++) { logA[t] = 0.f; logB[t] = 0.f; }

    // ---- logits (k path) ----
    #pragma unroll
    for (int c = 0; c < 8; c++) {
        float qa = base[(long)c * NPIX + pA] * SCALE;
        float qb = base[(long)c * NPIX + pB] * SCALE;
        float nbA[9], nbB[9];
        #pragma unroll
        for (int t = 0; t < 9; t++) {
            int dy = t / 3 - 1, dx = t % 3 - 1;
            nbA[t] = sk[c][ly + dy][lxA + dx];
            nbB[t] = sk[c][ly + dy][lxB + dx];
        }
        #pragma unroll
        for (int t = 0; t < 9; t++) {
            float bias = sb[c * 9 + t] + srpb[t];
            float kA = nbA[t] + bias;
            float kB = nbB[t] + bias;
            #pragma unroll
            for (int s = 0; s < 9; s++) {
                float w = sw1[c * 9 + t][s];
                kA += w * nbA[s];
                kB += w * nbB[s];
            }
            logA[t] += qa * kA;
            logB[t] += qb * kB;
        }
    }

    // ---- softmax over 9 ----
    float mA = logA[0], mB = logB[0];
    #pragma unroll
    for (int t = 1; t < 9; t++) { mA = fmaxf(mA, logA[t]); mB = fmaxf(mB, logB[t]); }
    float sumA = 0.f, sumB = 0.f;
    #pragma unroll
    for (int t = 0; t < 9; t++) {
        logA[t] = __expf(logA[t] - mA); sumA += logA[t];
        logB[t] = __expf(logB[t] - mB); sumB += logB[t];
    }
    float invA = 1.f / sumA, invB = 1.f / sumB;

    // ---- output (v path) ----
    #pragma unroll
    for (int c = 0; c < 8; c++) {
        float nbA[9], nbB[9];
        #pragma unroll
        for (int t = 0; t < 9; t++) {
            int dy = t / 3 - 1, dx = t % 3 - 1;
            nbA[t] = sv[c][ly + dy][lxA + dx];
            nbB[t] = sv[c][ly + dy][lxB + dx];
        }
        float oA = 0.f, oB = 0.f;
        #pragma unroll
        for (int t = 0; t < 9; t++) {
            float bias = sb[c * 9 + t];
            float vA = nbA[t] + bias;
            float vB = nbB[t] + bias;
            #pragma unroll
            for (int s = 0; s < 9; s++) {
                float w = sw1[c * 9 + t][s];
                vA += w * nbA[s];
                vB += w * nbB[s];
            }
            oA += logA[t] * vA;
            oB += logB[t] * vB;
        }
        long oOff = ((long)b * CRCH + nh * 8 + c) * NPIX;
        att[oOff + pA] = oA * invA;
        att[oOff + pB] = oB * invB;
    }
}

// ---------------------------------------------------------------------------
// kernel_launch
// inputs: 0:x 1:H22 2:W22 3:rel_pos_idx 4:rel_coords 5:qkv_w 6:qkv_b
//         7:dep_conv_b 8:dep_conv1_w 9:dep_conv1_b 10:rpb_table 11:proj_w 12:proj_b
// ---------------------------------------------------------------------------
extern "C" void kernel_launch(void* const* d_in, const int* in_sizes, int n_in,
                              void* d_out, int out_size)
{
    const float* x       = (const float*)d_in[0];
    const float* qkv_w   = (const float*)d_in[5];
    const float* qkv_b   = (const float*)d_in[6];
    const float* dep_b0  = (const float*)d_in[7];
    const float* W1      = (const float*)d_in[8];
    const float* dep_b1  = (const float*)d_in[9];
    const float* rpb     = (const float*)d_in[10];
    const float* proj_w  = (const float*)d_in[11];
    const float* proj_b  = (const float*)d_in[12];
    float* out = (float*)d_out;

    float* qkvbuf; cudaGetSymbolAddress((void**)&qkvbuf, g_qkv);
    float* attbuf; cudaGetSymbolAddress((void**)&attbuf, g_att);

    // GEMM1: (192 x 256) @ (256 x 4096) per batch  -> g_qkv
    sgemm_kernel<<<dim3(NPIX / 128, QKVC / 64, BATCH), 256>>>(
        qkv_w, x, qkv_b, qkvbuf,
        QKVC, NPIX, DIMC, (long)DIMC * NPIX, (long)QKVC * NPIX);

    // Slide attention -> g_att
    attn_kernel<<<dim3(2, 4, BATCH * NHEAD), 256>>>(
        qkvbuf, dep_b0, dep_b1, W1, rpb, attbuf);

    // GEMM3: (256 x 64) @ (64 x 4096) per batch -> d_out
    sgemm_kernel<<<dim3(NPIX / 128, DIMC / 64, BATCH), 256>>>(
        proj_w, attbuf, proj_b, out,
        DIMC, NPIX, CRCH, (long)CRCH * NPIX, (long)DIMC * NPIX);
}